// round 10
// baseline (speedup 1.0000x reference)
#include <cuda_runtime.h>

#define P_ 2
#define B_ 96
#define A_ 32
#define NT_ 24
#define N_ (B_*A_)             // 3072 atoms per pose
#define MD_ 4
#define MA_ 4
#define NPOLB_ 8
#define NSITES_ (P_*B_*NPOLB_) // 1536
#define SITES_PP_ (B_*NPOLB_)  // 768
#define SPB_ 256               // sites per tile
#define SGRP_ (SITES_PP_/SPB_) // 3 site-groups per pose
#define NTILE_ (P_*SGRP_*B_)   // 576 tiles
#define GRID_ 148              // persistent blocks (1 per SM, < 152 SMs)
#define TPB_ 1024
#define NGRP_ 4                // 256-thread tile groups per block
#define C_LK_ 0.0897935610625833f

// ---------------- device scratch (no allocations allowed) ----------------
__device__ float4 g_A0[NSITES_];   // xp.xyz, ri
__device__ float4 g_A1[NSITES_];   // water0.xyz, 1/lambda_i
__device__ float4 g_A2[NSITES_];   // water1.xyz, C_LK*dG_i/lambda_i
__device__ int2   g_I [NSITES_];   // valid, exclmask(intra-block pd<4)
__device__ unsigned long long g_bar = 0ULL;   // monotonic barrier counter

// ---------------- small vec helpers ----------------
__device__ __forceinline__ float3 ld3(const float* b, int i) {
    return make_float3(b[3*i], b[3*i+1], b[3*i+2]);
}
__device__ __forceinline__ float3 sub3(float3 a, float3 b) {
    return make_float3(a.x-b.x, a.y-b.y, a.z-b.z);
}
__device__ __forceinline__ float3 cross3(float3 a, float3 b) {
    return make_float3(a.y*b.z - a.z*b.y, a.z*b.x - a.x*b.z, a.x*b.y - a.y*b.x);
}
__device__ __forceinline__ float3 norm3(float3 v) {
    float inv = rsqrtf(v.x*v.x + v.y*v.y + v.z*v.z + 1e-12f);
    return make_float3(v.x*inv, v.y*inv, v.z*inv);
}

// ---------------- per-site geometry (phase A worker) ----------------
__device__ void prep_site(int t,
    const float* __restrict__ coords, const int* __restrict__ blockType,
    const int* __restrict__ bonds, const int* __restrict__ ranges,
    const int* __restrict__ n_donH, const int* __restrict__ n_acc,
    const int* __restrict__ donH, const int* __restrict__ don_hvy,
    const int* __restrict__ acc_inds, const int* __restrict__ hyb,
    const float* __restrict__ par4, const int* __restrict__ pathd,
    const float* __restrict__ wg, const float* __restrict__ sp2t,
    const float* __restrict__ sp3t, const float* __restrict__ ringt)
{
    int s  = t & (NPOLB_ - 1);
    int pb = t >> 3;
    int p  = pb / B_;
    int b  = pb - p*B_;
    int bt = blockType[p*B_ + b];
    const float* cb = coords + (size_t)(p*N_ + b*A_)*3;

    float wdist = wg[0], wang = wg[1];
    float3 w0, w1;
    int loc, valid;

    if (s < MD_) {                 // donor site
        int m  = s;
        valid  = (m < n_donH[bt]);
        int hi = don_hvy[bt*MD_ + m];
        int Hi = donH   [bt*MD_ + m];
        loc = hi;
        float3 hv = ld3(cb, hi);
        float3 Hx = ld3(cb, Hi);
        float3 dv = sub3(Hx, hv);
        float inv = rsqrtf(dv.x*dv.x + dv.y*dv.y + dv.z*dv.z + 1e-12f);
        float k = wdist * inv;
        w0 = make_float3(hv.x + k*dv.x, hv.y + k*dv.y, hv.z + k*dv.z);
        w1 = make_float3(1e6f, 1e6f, 1e6f);   // masked water #2 -> far away
    } else {                       // acceptor site
        int m  = s - MD_;
        valid  = (m < n_acc[bt]);
        int ai = acc_inds[bt*MA_ + m];
        loc = ai;
        int r0 = ranges[(bt*A_ + ai)*2];
        int b1 = bonds [(bt*A_ + r0)*2 + 1];
        int r1 = ranges[(bt*A_ + b1)*2];
        int b2 = bonds [(bt*A_ + r1)*2 + 1];
        float3 c  = ld3(cb, ai);
        float3 bx = ld3(cb, b1);
        float3 ax = ld3(cb, b2);
        float3 e1 = norm3(sub3(c, bx));
        float3 nr = norm3(cross3(sub3(bx, ax), e1));
        float3 e2 = cross3(nr, e1);
        int h = hyb[bt*MA_ + m];
        const float* tt = (h == 0) ? sp2t : (h == 1) ? sp3t : ringt;
        float st, ct;
        sincosf(wang, &st, &ct);
        float k1 = -wdist * ct;
        float ks =  wdist * st;
        float s0c, c0c, s1c, c1c;
        sincosf(tt[0], &s0c, &c0c);
        sincosf(tt[1], &s1c, &c1c);
        w0 = make_float3(c.x + k1*e1.x + ks*c0c*e2.x + ks*s0c*nr.x,
                         c.y + k1*e1.y + ks*c0c*e2.y + ks*s0c*nr.y,
                         c.z + k1*e1.z + ks*c0c*e2.z + ks*s0c*nr.z);
        w1 = make_float3(c.x + k1*e1.x + ks*c1c*e2.x + ks*s1c*nr.x,
                         c.y + k1*e1.y + ks*c1c*e2.y + ks*s1c*nr.y,
                         c.z + k1*e1.z + ks*c1c*e2.z + ks*s1c*nr.z);
    }

    const float* pr = par4 + (size_t)(bt*A_ + loc)*4;
    float ri = pr[0], dgi = pr[1], lami = pr[2];
    float il = 1.0f / lami;
    float3 xp = ld3(cb, loc);

    // intra-block exclusion mask: bit j set if path_distance(loc, j) < 4
    unsigned ex = 0;
    const int4* pd4 = (const int4*)(pathd + (size_t)(bt*A_ + loc)*A_);
    #pragma unroll
    for (int k = 0; k < A_/4; k++) {
        int4 v = pd4[k];
        ex |= (unsigned)(v.x < 4) << (4*k);
        ex |= (unsigned)(v.y < 4) << (4*k + 1);
        ex |= (unsigned)(v.z < 4) << (4*k + 2);
        ex |= (unsigned)(v.w < 4) << (4*k + 3);
    }

    g_A0[t] = make_float4(xp.x, xp.y, xp.z, ri);
    g_A1[t] = make_float4(w0.x, w0.y, w0.z, il);
    g_A2[t] = make_float4(w1.x, w1.y, w1.z, C_LK_ * dgi * il);
    g_I [t] = make_int2(valid, (int)ex);
}

// ---------------- single persistent fused kernel ----------------
__global__ __launch_bounds__(TPB_, 1) void fused_kernel(
    const float* __restrict__ coords,     // (P,N,3)
    const int*   __restrict__ blockType,  // (P,B)
    const int*   __restrict__ minsep,     // (P,B,B)
    const int*   __restrict__ bonds,
    const int*   __restrict__ ranges,
    const int*   __restrict__ n_donH,
    const int*   __restrict__ n_acc,
    const int*   __restrict__ donH,
    const int*   __restrict__ don_hvy,
    const int*   __restrict__ acc_inds,
    const int*   __restrict__ hyb,
    const int*   __restrict__ is_h,       // (NT,A)
    const float* __restrict__ par4,       // (NT,A,4)
    const int*   __restrict__ pathd,
    const float* __restrict__ gp,         // cutoff, ramp2, d2_low
    const float* __restrict__ wg,
    const float* __restrict__ sp2t,
    const float* __restrict__ sp3t,
    const float* __restrict__ ringt,
    float* __restrict__ out)
{
    __shared__ float4   s_xyzr[NGRP_][A_];
    __shared__ float    s_vol [NGRP_][A_];
    __shared__ unsigned s_hvy [NGRP_];
    __shared__ float    s_acc [2*P_];

    int tid  = threadIdx.x;
    int grp  = tid >> 8;
    int gtid = tid & 255;
    int tile = blockIdx.x * NGRP_ + grp;
    bool act = tile < NTILE_;

    // decode tile -> (pose, site-group, atom chunk)
    int p = 0, sg = 0, cbk = 0;
    if (act) {
        p = tile / (SGRP_*B_);
        int r = tile - p*(SGRP_*B_);
        sg  = r / B_;
        cbk = r - sg*B_;
    }

    // ---- pre-barrier: zero accumulators ----
    if (tid < 2*P_) {
        s_acc[tid] = 0.0f;
        if (blockIdx.x == 0) out[tid] = 0.0f;
    }

    // ---- pre-barrier: fill this group's tile smem (first warp of group) ----
    if (act && gtid < 32) {
        int bt = blockType[p*B_ + cbk];
        const float* c  = coords + (size_t)(p*N_ + cbk*A_ + gtid)*3;
        const float* pr = par4 + (size_t)(bt*A_ + gtid)*4;
        float v = is_h[bt*A_ + gtid] ? 0.0f : pr[3];
        s_xyzr[grp][gtid] = make_float4(c[0], c[1], c[2], pr[0]);
        s_vol [grp][gtid] = v;
        unsigned hm = __ballot_sync(0xffffffffu, v != 0.0f);
        if (gtid == 0) s_hvy[grp] = hm;
    }

    // ---- pre-barrier: per-thread site bookkeeping (inputs only) ----
    int sloc = sg*SPB_ + gtid;           // site within pose
    int b_i  = sloc >> 3;
    int sid  = p*SITES_PP_ + sloc;
    bool same = (b_i == cbk);
    int sepF = 0;
    if (act) sepF = same ? 6 : __ldg(&minsep[(p*B_ + b_i)*B_ + cbk]);

    // ---- pre-barrier: site geometry (blocks 0..1 cover 1536 sites) ----
    {
        int g = blockIdx.x * TPB_ + tid;
        if (g < NSITES_)
            prep_site(g, coords, blockType, bonds, ranges, n_donH, n_acc,
                      donH, don_hvy, acc_inds, hyb, par4, pathd,
                      wg, sp2t, sp3t, ringt);
    }

    // ---- grid-wide barrier (monotonic counter: graph-replay safe) ----
    __syncthreads();
    if (tid == 0) {
        __threadfence();
        unsigned long long my = atomicAdd(&g_bar, 1ULL);
        unsigned long long target = my - (my % GRID_) + GRID_;
        volatile unsigned long long* vb = &g_bar;
        while (*vb < target) __nanosleep(64);
    }
    __syncthreads();
    __threadfence();

    // ---- phase B: pair loop, one tile per 256-thread group ----
    float cutoff2  = gp[0]*gp[0];
    float inv_ramp = 1.0f / gp[1];
    float thr      = gp[2] + gp[1];      // d2_low + ramp2

    float sum0 = 0.0f, sum1 = 0.0f;

    if (act) {
        int2 I = g_I[sid];
        if (I.x && sepF >= 4) {
            float4 A0 = g_A0[sid];

            // phase 1: distance mask only
            unsigned dmask = 0;
            #pragma unroll
            for (int j = 0; j < A_; j++) {
                float4 q = s_xyzr[grp][j];
                float dx = A0.x - q.x, dy = A0.y - q.y, dz = A0.z - q.z;
                float d2 = fmaf(dx, dx, fmaf(dy, dy, dz*dz));
                if (d2 < cutoff2) dmask |= (1u << j);
            }
            unsigned m = dmask & s_hvy[grp];
            if (same) m &= ~(unsigned)I.y;

            // phase 2: heavy path on surviving pairs only
            if (m) {
                float4 A1 = g_A1[sid];
                float4 A2 = g_A2[sid];
                do {
                    int j = __ffs(m) - 1;
                    m &= m - 1;
                    float4 q = s_xyzr[grp][j];
                    float dx = A0.x - q.x, dy = A0.y - q.y, dz = A0.z - q.z;
                    float d2 = fmaxf(fmaf(dx, dx, fmaf(dy, dy, dz*dz)), 0.01f);
                    float irt = rsqrtf(d2);
                    float d   = d2 * irt;            // sqrt(d2)
                    float x   = (d - (A0.w + q.w)) * A1.w;
                    float lk  = A2.w * s_vol[grp][j] * __expf(-x*x) * (irt*irt);
                    sum0 += lk;
                    float ex = A1.x - q.x, ey = A1.y - q.y, ez = A1.z - q.z;
                    float dw0 = fmaf(ex, ex, fmaf(ey, ey, ez*ez));
                    float fx = A2.x - q.x, fy = A2.y - q.y, fz = A2.z - q.z;
                    float dw1 = fmaf(fx, fx, fmaf(fy, fy, fz*fz));
                    float dwmin = fminf(dw0, dw1);
                    float wt = __saturatef((thr - dwmin) * inv_ramp);
                    float frac = wt*wt*(3.0f - 2.0f*wt);
                    sum1 = fmaf(lk, frac, sum1);
                } while (m);
            }
        }
    }

    // ---- reduction: warp shuffle -> smem atomics -> global atomics ----
    #pragma unroll
    for (int o = 16; o; o >>= 1) {
        sum0 += __shfl_xor_sync(0xffffffffu, sum0, o);
        sum1 += __shfl_xor_sync(0xffffffffu, sum1, o);
    }
    if (act && (tid & 31) == 0) {
        if (sum0 != 0.0f || sum1 != 0.0f) {
            atomicAdd(&s_acc[p],      sum0);
            atomicAdd(&s_acc[P_ + p], sum1);
        }
    }
    __syncthreads();
    if (tid < 2*P_) atomicAdd(&out[tid], s_acc[tid]);
}

// ---------------- launch ----------------
extern "C" void kernel_launch(void* const* d_in, const int* in_sizes, int n_in,
                              void* d_out, int out_size)
{
    const float* coords    = (const float*)d_in[0];
    const int*   blockType = (const int*)  d_in[1];
    const int*   minsep    = (const int*)  d_in[2];
    // d_in[3] = bt_n_atoms (unused: always A)
    const int*   bonds     = (const int*)  d_in[4];
    const int*   ranges    = (const int*)  d_in[5];
    const int*   n_donH    = (const int*)  d_in[6];
    const int*   n_acc     = (const int*)  d_in[7];
    const int*   donH      = (const int*)  d_in[8];
    const int*   don_hvy   = (const int*)  d_in[9];
    const int*   acc_inds  = (const int*)  d_in[10];
    const int*   hyb       = (const int*)  d_in[11];
    const int*   is_h      = (const int*)  d_in[12];
    const float* par4      = (const float*)d_in[13];
    const int*   pathd     = (const int*)  d_in[14];
    const float* gp        = (const float*)d_in[15];
    const float* wg        = (const float*)d_in[16];
    const float* sp2t      = (const float*)d_in[17];
    const float* sp3t      = (const float*)d_in[18];
    const float* ringt     = (const float*)d_in[19];

    fused_kernel<<<GRID_, TPB_>>>(
        coords, blockType, minsep, bonds, ranges, n_donH, n_acc,
        donH, don_hvy, acc_inds, hyb, is_h, par4, pathd,
        gp, wg, sp2t, sp3t, ringt, (float*)d_out);
}

// round 11
// speedup vs baseline: 1.1705x; 1.1705x over previous
#include <cuda_runtime.h>

#define P_ 2
#define B_ 96
#define A_ 32
#define NT_ 24
#define N_ (B_*A_)             // 3072 atoms per pose
#define MD_ 4
#define MA_ 4
#define NPOLB_ 8
#define NSITES_ (P_*B_*NPOLB_) // 1536
#define SITES_PP_ (B_*NPOLB_)  // 768
#define SPB_ 256               // sites per pair-block
#define SGRP_ (SITES_PP_/SPB_) // 3 site-groups per pose
#define NBLK_ (P_*SGRP_*B_)    // 576 pair blocks
#define C_LK_ 0.0897935610625833f

// ---------------- device scratch (no allocations allowed) ----------------
__device__ float4 g_A0[NSITES_];   // xp.xyz (1e8 if invalid), ri
__device__ float4 g_A1[NSITES_];   // water0.xyz, 1/lambda_i
__device__ float4 g_A2[NSITES_];   // water1.xyz, C_LK*dG_i/lambda_i
__device__ int    g_ex[NSITES_];   // intra-block exclusion mask (pd<4)

// ---------------- small vec helpers ----------------
__device__ __forceinline__ float3 ld3(const float* b, int i) {
    return make_float3(b[3*i], b[3*i+1], b[3*i+2]);
}
__device__ __forceinline__ float3 sub3(float3 a, float3 b) {
    return make_float3(a.x-b.x, a.y-b.y, a.z-b.z);
}
__device__ __forceinline__ float3 cross3(float3 a, float3 b) {
    return make_float3(a.y*b.z - a.z*b.y, a.z*b.x - a.x*b.z, a.x*b.y - a.y*b.x);
}
__device__ __forceinline__ float3 norm3(float3 v) {
    float inv = rsqrtf(v.x*v.x + v.y*v.y + v.z*v.z + 1e-12f);
    return make_float3(v.x*inv, v.y*inv, v.z*inv);
}

// ---------------- phase 1: per-site geometry + out=0 ----------------
__global__ void prep_kernel(
    const float* __restrict__ coords,      // (P,N,3)
    const int*   __restrict__ blockType,   // (P,B)
    const int*   __restrict__ bonds,       // (NT,A,2)
    const int*   __restrict__ ranges,      // (NT,A,2)
    const int*   __restrict__ n_donH,      // (NT,)
    const int*   __restrict__ n_acc,       // (NT,)
    const int*   __restrict__ donH,        // (NT,MD)
    const int*   __restrict__ don_hvy,     // (NT,MD)
    const int*   __restrict__ acc_inds,    // (NT,MA)
    const int*   __restrict__ hyb,         // (NT,MA)
    const float* __restrict__ par4,        // (NT,A,4)
    const int*   __restrict__ pathd,       // (NT,A,A)
    const float* __restrict__ wg,          // wdist, wang
    const float* __restrict__ sp2t,
    const float* __restrict__ sp3t,
    const float* __restrict__ ringt,
    float* __restrict__ out)
{
    int t = blockIdx.x * blockDim.x + threadIdx.x;
    if (t < 2*P_) out[t] = 0.0f;            // zero accumulators every call
    if (t < NSITES_) {
        int s  = t & (NPOLB_ - 1);
        int pb = t >> 3;
        int p  = pb / B_;
        int b  = pb - p*B_;
        int bt = blockType[p*B_ + b];
        const float* cb = coords + (size_t)(p*N_ + b*A_)*3;

        float wdist = wg[0], wang = wg[1];
        float3 w0, w1;
        int loc, valid;

        if (s < MD_) {                 // donor site
            int m  = s;
            valid  = (m < n_donH[bt]);
            int hi = don_hvy[bt*MD_ + m];
            int Hi = donH   [bt*MD_ + m];
            loc = hi;
            float3 hv = ld3(cb, hi);
            float3 Hx = ld3(cb, Hi);
            float3 dv = sub3(Hx, hv);
            float inv = rsqrtf(dv.x*dv.x + dv.y*dv.y + dv.z*dv.z + 1e-12f);
            float k = wdist * inv;
            w0 = make_float3(hv.x + k*dv.x, hv.y + k*dv.y, hv.z + k*dv.z);
            w1 = make_float3(1e6f, 1e6f, 1e6f);   // masked water #2 -> far away
        } else {                       // acceptor site
            int m  = s - MD_;
            valid  = (m < n_acc[bt]);
            int ai = acc_inds[bt*MA_ + m];
            loc = ai;
            int r0 = ranges[(bt*A_ + ai)*2];
            int b1 = bonds [(bt*A_ + r0)*2 + 1];
            int r1 = ranges[(bt*A_ + b1)*2];
            int b2 = bonds [(bt*A_ + r1)*2 + 1];
            float3 c  = ld3(cb, ai);
            float3 bx = ld3(cb, b1);
            float3 ax = ld3(cb, b2);
            float3 e1 = norm3(sub3(c, bx));
            float3 nr = norm3(cross3(sub3(bx, ax), e1));
            float3 e2 = cross3(nr, e1);
            int h = hyb[bt*MA_ + m];
            const float* tt = (h == 0) ? sp2t : (h == 1) ? sp3t : ringt;
            float st, ct;
            sincosf(wang, &st, &ct);
            float k1 = -wdist * ct;
            float ks =  wdist * st;
            float s0c, c0c, s1c, c1c;
            sincosf(tt[0], &s0c, &c0c);
            sincosf(tt[1], &s1c, &c1c);
            w0 = make_float3(c.x + k1*e1.x + ks*c0c*e2.x + ks*s0c*nr.x,
                             c.y + k1*e1.y + ks*c0c*e2.y + ks*s0c*nr.y,
                             c.z + k1*e1.z + ks*c0c*e2.z + ks*s0c*nr.z);
            w1 = make_float3(c.x + k1*e1.x + ks*c1c*e2.x + ks*s1c*nr.x,
                             c.y + k1*e1.y + ks*c1c*e2.y + ks*s1c*nr.y,
                             c.z + k1*e1.z + ks*c1c*e2.z + ks*s1c*nr.z);
        }

        const float* pr = par4 + (size_t)(bt*A_ + loc)*4;
        float ri = pr[0], dgi = pr[1], lami = pr[2];
        float il = 1.0f / lami;
        float3 xp = ld3(cb, loc);

        // invalid sites: park far away -> never pass the distance cutoff
        if (!valid) { xp = make_float3(1e8f, 1e8f, 1e8f); }

        // intra-block exclusion mask: bit j set if path_distance(loc, j) < 4
        unsigned ex = 0;
        const int4* pd4 = (const int4*)(pathd + (size_t)(bt*A_ + loc)*A_);
        #pragma unroll
        for (int k = 0; k < A_/4; k++) {
            int4 v = pd4[k];
            ex |= (unsigned)(v.x < 4) << (4*k);
            ex |= (unsigned)(v.y < 4) << (4*k + 1);
            ex |= (unsigned)(v.z < 4) << (4*k + 2);
            ex |= (unsigned)(v.w < 4) << (4*k + 3);
        }

        g_A0[t] = make_float4(xp.x, xp.y, xp.z, ri);
        g_A1[t] = make_float4(w0.x, w0.y, w0.z, il);
        g_A2[t] = make_float4(w1.x, w1.y, w1.z, C_LK_ * dgi * il);
        g_ex[t] = (int)ex;
    }

    // release dependent (pair) kernel as early as possible
    __threadfence();
#if defined(__CUDA_ARCH__) && (__CUDA_ARCH__ >= 900)
    cudaTriggerProgrammaticLaunchCompletion();
#endif
}

// ---------------- phase 2: 256 sites x one 32-atom chunk per block ----------
__global__ __launch_bounds__(SPB_) void pair_kernel(
    const float* __restrict__ coords,     // (P,N,3)
    const int*   __restrict__ blockType,  // (P,B)
    const int*   __restrict__ minsep,     // (P,B,B)
    const int*   __restrict__ is_h,       // (NT,A)
    const float* __restrict__ par4,       // (NT,A,4)
    const float* __restrict__ gp,         // cutoff, ramp2, d2_low
    float* __restrict__ out)
{
    __shared__ float4 s_xyzr[A_];
    __shared__ float  s_vol [A_];
    __shared__ float2 s_red[SPB_/32];

    int bid  = blockIdx.x;
    int cb   = bid % B_;                 // atom chunk (pose-block)
    int rest = bid / B_;
    int sg   = rest % SGRP_;             // site group
    int p    = rest / SGRP_;             // pose
    int tid  = threadIdx.x;

    // ---- PDL prefix: everything below reads only raw inputs ----
    if (tid < A_) {
        int bt = blockType[p*B_ + cb];
        const float* c  = coords + (size_t)(p*N_ + cb*A_ + tid)*3;
        const float* pr = par4 + (size_t)(bt*A_ + tid)*4;
        s_xyzr[tid] = make_float4(c[0], c[1], c[2], pr[0]);
        s_vol [tid] = is_h[bt*A_ + tid] ? 0.0f : pr[3];
    }

    int sloc = sg*SPB_ + tid;            // site within pose
    int b_i  = sloc >> 3;
    int sid  = p*SITES_PP_ + sloc;
    bool same = (b_i == cb);
    int sepF = same ? 6 : __ldg(&minsep[(p*B_ + b_i)*B_ + cb]);

    float cutoff2  = gp[0]*gp[0];
    float inv_ramp = 1.0f / gp[1];
    float thr      = gp[2] + gp[1];      // d2_low + ramp2

    __syncthreads();

    // ---- wait for prep's outputs ----
#if defined(__CUDA_ARCH__) && (__CUDA_ARCH__ >= 900)
    cudaGridDependencySynchronize();
#endif

    float sum0 = 0.0f, sum1 = 0.0f;

    if (sepF >= 4) {
        float4 A0 = g_A0[sid];
        float4 A1 = g_A1[sid];
        float4 A2 = g_A2[sid];
        unsigned ex = same ? (unsigned)g_ex[sid] : 0u;

        #pragma unroll 8
        for (int j = 0; j < A_; j++) {
            float4 q = s_xyzr[j];
            float dx = A0.x - q.x, dy = A0.y - q.y, dz = A0.z - q.z;
            float d2 = fmaf(dx, dx, fmaf(dy, dy, dz*dz));
            d2 = fmaxf(d2, 0.01f);
            float v = s_vol[j];
            if (d2 < cutoff2 && v != 0.0f && !((ex >> j) & 1u)) {
                float irt = rsqrtf(d2);
                float d   = d2 * irt;            // sqrt(d2)
                float x   = (d - (A0.w + q.w)) * A1.w;
                float lk  = A2.w * v * __expf(-x*x) * (irt*irt);
                sum0 += lk;
                float ex0 = A1.x - q.x, ey0 = A1.y - q.y, ez0 = A1.z - q.z;
                float dw0 = fmaf(ex0, ex0, fmaf(ey0, ey0, ez0*ez0));
                float fx = A2.x - q.x, fy = A2.y - q.y, fz = A2.z - q.z;
                float dw1 = fmaf(fx, fx, fmaf(fy, fy, fz*fz));
                float dwmin = fminf(dw0, dw1);
                float wt = __saturatef((thr - dwmin) * inv_ramp);
                float frac = wt*wt*(3.0f - 2.0f*wt);
                sum1 = fmaf(lk, frac, sum1);
            }
        }
    }

    // ---- block reduction -> 2 atomics ----
    int lane = tid & 31, wid = tid >> 5;
    #pragma unroll
    for (int o = 16; o; o >>= 1) {
        sum0 += __shfl_xor_sync(0xffffffffu, sum0, o);
        sum1 += __shfl_xor_sync(0xffffffffu, sum1, o);
    }
    if (lane == 0) s_red[wid] = make_float2(sum0, sum1);
    __syncthreads();
    if (wid == 0) {
        float a = (lane < SPB_/32) ? s_red[lane].x : 0.0f;
        float b = (lane < SPB_/32) ? s_red[lane].y : 0.0f;
        #pragma unroll
        for (int o = 4; o; o >>= 1) {
            a += __shfl_xor_sync(0xffffffffu, a, o);
            b += __shfl_xor_sync(0xffffffffu, b, o);
        }
        if (lane == 0) {
            atomicAdd(&out[p],      a);   // component 0, pose p
            atomicAdd(&out[P_ + p], b);   // component 1, pose p
        }
    }
}

// ---------------- launch ----------------
extern "C" void kernel_launch(void* const* d_in, const int* in_sizes, int n_in,
                              void* d_out, int out_size)
{
    const float* coords    = (const float*)d_in[0];
    const int*   blockType = (const int*)  d_in[1];
    const int*   minsep    = (const int*)  d_in[2];
    // d_in[3] = bt_n_atoms (unused: always A)
    const int*   bonds     = (const int*)  d_in[4];
    const int*   ranges    = (const int*)  d_in[5];
    const int*   n_donH    = (const int*)  d_in[6];
    const int*   n_acc     = (const int*)  d_in[7];
    const int*   donH      = (const int*)  d_in[8];
    const int*   don_hvy   = (const int*)  d_in[9];
    const int*   acc_inds  = (const int*)  d_in[10];
    const int*   hyb       = (const int*)  d_in[11];
    const int*   is_h      = (const int*)  d_in[12];
    const float* par4      = (const float*)d_in[13];
    const int*   pathd     = (const int*)  d_in[14];
    const float* gp        = (const float*)d_in[15];
    const float* wg        = (const float*)d_in[16];
    const float* sp2t      = (const float*)d_in[17];
    const float* sp3t      = (const float*)d_in[18];
    const float* ringt     = (const float*)d_in[19];
    float* out = (float*)d_out;

    prep_kernel<<<(NSITES_ + 255)/256, 256>>>(
        coords, blockType, bonds, ranges, n_donH, n_acc,
        donH, don_hvy, acc_inds, hyb, par4, pathd,
        wg, sp2t, sp3t, ringt, out);

    // pair kernel with programmatic dependent launch: prefix overlaps prep
    cudaLaunchConfig_t cfg = {};
    cfg.gridDim  = dim3(NBLK_, 1, 1);
    cfg.blockDim = dim3(SPB_, 1, 1);
    cfg.dynamicSmemBytes = 0;
    cfg.stream = 0;
    cudaLaunchAttribute attrs[1];
    attrs[0].id = cudaLaunchAttributeProgrammaticStreamSerialization;
    attrs[0].val.programmaticStreamSerializationAllowed = 1;
    cfg.attrs = attrs;
    cfg.numAttrs = 1;
    cudaLaunchKernelEx(&cfg, pair_kernel,
                       coords, blockType, minsep, is_h, par4, gp, out);
}

// round 13
// speedup vs baseline: 1.5528x; 1.3266x over previous
#include <cuda_runtime.h>

#define P_ 2
#define B_ 96
#define A_ 32
#define NT_ 24
#define N_ (B_*A_)             // 3072 atoms per pose
#define MD_ 4
#define MA_ 4
#define NPOLB_ 8
#define NSITES_ (P_*B_*NPOLB_) // 1536
#define SITES_PP_ (B_*NPOLB_)  // 768
#define SPB_ 256               // sites per pair-block
#define SGRP_ (SITES_PP_/SPB_) // 3 site-groups per pose
#define NBLK_ (P_*SGRP_*B_)    // 576 pair blocks
#define C_LK_ 0.0897935610625833f

// ---------------- device scratch (no allocations allowed) ----------------
__device__ float4 g_A0[NSITES_];   // xp.xyz (1e8 if invalid), ri
__device__ float4 g_A1[NSITES_];   // water0.xyz, 1/lambda_i
__device__ float4 g_A2[NSITES_];   // water1.xyz, C_LK*dG_i/lambda_i
__device__ int    g_ex[NSITES_];   // intra-block exclusion mask (pd<4)

// ---------------- small vec helpers ----------------
__device__ __forceinline__ float3 ld3(const float* b, int i) {
    return make_float3(b[3*i], b[3*i+1], b[3*i+2]);
}
__device__ __forceinline__ float3 sub3(float3 a, float3 b) {
    return make_float3(a.x-b.x, a.y-b.y, a.z-b.z);
}
__device__ __forceinline__ float3 cross3(float3 a, float3 b) {
    return make_float3(a.y*b.z - a.z*b.y, a.z*b.x - a.x*b.z, a.x*b.y - a.y*b.x);
}
__device__ __forceinline__ float3 norm3(float3 v) {
    float inv = rsqrtf(v.x*v.x + v.y*v.y + v.z*v.z + 1e-12f);
    return make_float3(v.x*inv, v.y*inv, v.z*inv);
}

// ---------------- phase 1: per-site geometry + out=0 ----------------
__global__ void prep_kernel(
    const float* __restrict__ coords,      // (P,N,3)
    const int*   __restrict__ blockType,   // (P,B)
    const int*   __restrict__ bonds,       // (NT,A,2)
    const int*   __restrict__ ranges,      // (NT,A,2)
    const int*   __restrict__ n_donH,      // (NT,)
    const int*   __restrict__ n_acc,       // (NT,)
    const int*   __restrict__ donH,        // (NT,MD)
    const int*   __restrict__ don_hvy,     // (NT,MD)
    const int*   __restrict__ acc_inds,    // (NT,MA)
    const int*   __restrict__ hyb,         // (NT,MA)
    const float* __restrict__ par4,        // (NT,A,4)
    const int*   __restrict__ pathd,       // (NT,A,A)
    const float* __restrict__ wg,          // wdist, wang
    const float* __restrict__ sp2t,
    const float* __restrict__ sp3t,
    const float* __restrict__ ringt,
    float* __restrict__ out)
{
    int t = blockIdx.x * blockDim.x + threadIdx.x;
    if (t < 2*P_) out[t] = 0.0f;            // zero accumulators every call
    if (t < NSITES_) {
        int s  = t & (NPOLB_ - 1);
        int pb = t >> 3;
        int p  = pb / B_;
        int b  = pb - p*B_;
        int bt = blockType[p*B_ + b];
        const float* cb = coords + (size_t)(p*N_ + b*A_)*3;

        float wdist = wg[0], wang = wg[1];
        float3 w0, w1;
        int loc, valid;

        if (s < MD_) {                 // donor site
            int m  = s;
            valid  = (m < n_donH[bt]);
            int hi = don_hvy[bt*MD_ + m];
            int Hi = donH   [bt*MD_ + m];
            loc = hi;
            float3 hv = ld3(cb, hi);
            float3 Hx = ld3(cb, Hi);
            float3 dv = sub3(Hx, hv);
            float inv = rsqrtf(dv.x*dv.x + dv.y*dv.y + dv.z*dv.z + 1e-12f);
            float k = wdist * inv;
            w0 = make_float3(hv.x + k*dv.x, hv.y + k*dv.y, hv.z + k*dv.z);
            w1 = make_float3(1e6f, 1e6f, 1e6f);   // masked water #2 -> far away
        } else {                       // acceptor site
            int m  = s - MD_;
            valid  = (m < n_acc[bt]);
            int ai = acc_inds[bt*MA_ + m];
            loc = ai;
            int r0 = ranges[(bt*A_ + ai)*2];
            int b1 = bonds [(bt*A_ + r0)*2 + 1];
            int r1 = ranges[(bt*A_ + b1)*2];
            int b2 = bonds [(bt*A_ + r1)*2 + 1];
            float3 c  = ld3(cb, ai);
            float3 bx = ld3(cb, b1);
            float3 ax = ld3(cb, b2);
            float3 e1 = norm3(sub3(c, bx));
            float3 nr = norm3(cross3(sub3(bx, ax), e1));
            float3 e2 = cross3(nr, e1);
            int h = hyb[bt*MA_ + m];
            const float* tt = (h == 0) ? sp2t : (h == 1) ? sp3t : ringt;
            float st, ct;
            __sincosf(wang, &st, &ct);
            float k1 = -wdist * ct;
            float ks =  wdist * st;
            float s0c, c0c, s1c, c1c;
            __sincosf(tt[0], &s0c, &c0c);
            __sincosf(tt[1], &s1c, &c1c);
            w0 = make_float3(c.x + k1*e1.x + ks*c0c*e2.x + ks*s0c*nr.x,
                             c.y + k1*e1.y + ks*c0c*e2.y + ks*s0c*nr.y,
                             c.z + k1*e1.z + ks*c0c*e2.z + ks*s0c*nr.z);
            w1 = make_float3(c.x + k1*e1.x + ks*c1c*e2.x + ks*s1c*nr.x,
                             c.y + k1*e1.y + ks*c1c*e2.y + ks*s1c*nr.y,
                             c.z + k1*e1.z + ks*c1c*e2.z + ks*s1c*nr.z);
        }

        const float* pr = par4 + (size_t)(bt*A_ + loc)*4;
        float ri = pr[0], dgi = pr[1], lami = pr[2];
        float il = 1.0f / lami;
        float3 xp = ld3(cb, loc);

        // invalid sites: park far away -> never pass the distance cutoff
        if (!valid) { xp = make_float3(1e8f, 1e8f, 1e8f); }

        // intra-block exclusion mask: bit j set if path_distance(loc, j) < 4
        unsigned ex = 0;
        const int4* pd4 = (const int4*)(pathd + (size_t)(bt*A_ + loc)*A_);
        #pragma unroll
        for (int k = 0; k < A_/4; k++) {
            int4 v = pd4[k];
            ex |= (unsigned)(v.x < 4) << (4*k);
            ex |= (unsigned)(v.y < 4) << (4*k + 1);
            ex |= (unsigned)(v.z < 4) << (4*k + 2);
            ex |= (unsigned)(v.w < 4) << (4*k + 3);
        }

        g_A0[t] = make_float4(xp.x, xp.y, xp.z, ri);
        g_A1[t] = make_float4(w0.x, w0.y, w0.z, il);
        g_A2[t] = make_float4(w1.x, w1.y, w1.z, C_LK_ * dgi * il);
        g_ex[t] = (int)ex;
    }

    // release dependent (pair) kernel
    __threadfence();
#if defined(__CUDA_ARCH__) && (__CUDA_ARCH__ >= 900)
    cudaTriggerProgrammaticLaunchCompletion();
#endif
}

// ---------------- phase 2: 256 sites x one 32-atom chunk per block ----------
__global__ __launch_bounds__(SPB_) void pair_kernel(
    const float* __restrict__ coords,     // (P,N,3)
    const int*   __restrict__ blockType,  // (P,B)
    const int*   __restrict__ minsep,     // (P,B,B)
    const int*   __restrict__ is_h,       // (NT,A)
    const float* __restrict__ par4,       // (NT,A,4)
    const float* __restrict__ gp,         // cutoff, ramp2, d2_low
    float* __restrict__ out)
{
    __shared__ float4   s_xyzr[A_];
    __shared__ float    s_vol [A_];
    __shared__ unsigned s_hvy;
    __shared__ float2   s_red[SPB_/32];

    int bid  = blockIdx.x;
    int cb   = bid % B_;                 // atom chunk (pose-block)
    int rest = bid / B_;
    int sg   = rest % SGRP_;             // site group
    int p    = rest / SGRP_;             // pose
    int tid  = threadIdx.x;

    // ---- PDL prefix: everything below reads only raw inputs ----
    if (tid < 32) {
        int bt = blockType[p*B_ + cb];
        const float* c  = coords + (size_t)(p*N_ + cb*A_ + tid)*3;
        const float* pr = par4 + (size_t)(bt*A_ + tid)*4;
        float v = is_h[bt*A_ + tid] ? 0.0f : pr[3];
        s_xyzr[tid] = make_float4(c[0], c[1], c[2], pr[0]);
        s_vol [tid] = v;
        unsigned hm = __ballot_sync(0xffffffffu, v != 0.0f);
        if (tid == 0) s_hvy = hm;
    }

    int sloc = sg*SPB_ + tid;            // site within pose
    int b_i  = sloc >> 3;
    int sid  = p*SITES_PP_ + sloc;
    bool same = (b_i == cb);
    int sepF = same ? 6 : __ldg(&minsep[(p*B_ + b_i)*B_ + cb]);

    float cutoff2  = gp[0]*gp[0];
    float inv_ramp = 1.0f / gp[1];
    float thr      = gp[2] + gp[1];      // d2_low + ramp2

    __syncthreads();
    unsigned hvymask = s_hvy;

    // ---- wait for prep's outputs ----
#if defined(__CUDA_ARCH__) && (__CUDA_ARCH__ >= 900)
    cudaGridDependencySynchronize();
#endif

    float sum0 = 0.0f, sum1 = 0.0f;

    if (sepF >= 4) {
        float4 A0 = g_A0[sid];

        // ---- phase 1: cheap distance mask, fully unrolled ----
        unsigned dmask = 0;
        #pragma unroll
        for (int j = 0; j < A_; j++) {
            float4 q = s_xyzr[j];
            float dx = A0.x - q.x, dy = A0.y - q.y, dz = A0.z - q.z;
            float d2 = fmaf(dx, dx, fmaf(dy, dy, dz*dz));
            if (d2 < cutoff2) dmask |= (1u << j);
        }
        unsigned m = dmask & hvymask;
        if (same) m &= ~(unsigned)g_ex[sid];

        // ---- phase 2: heavy path on surviving pairs only ----
        if (m) {
            float4 A1 = g_A1[sid];
            float4 A2 = g_A2[sid];
            do {
                int j = __ffs(m) - 1;
                m &= m - 1;
                float4 q = s_xyzr[j];
                float dx = A0.x - q.x, dy = A0.y - q.y, dz = A0.z - q.z;
                float d2 = fmaxf(fmaf(dx, dx, fmaf(dy, dy, dz*dz)), 0.01f);
                float irt = rsqrtf(d2);
                float d   = d2 * irt;            // sqrt(d2)
                float x   = (d - (A0.w + q.w)) * A1.w;
                float lk  = A2.w * s_vol[j] * __expf(-x*x) * (irt*irt);
                sum0 += lk;
                float ex0 = A1.x - q.x, ey0 = A1.y - q.y, ez0 = A1.z - q.z;
                float dw0 = fmaf(ex0, ex0, fmaf(ey0, ey0, ez0*ez0));
                float fx = A2.x - q.x, fy = A2.y - q.y, fz = A2.z - q.z;
                float dw1 = fmaf(fx, fx, fmaf(fy, fy, fz*fz));
                float dwmin = fminf(dw0, dw1);
                float wt = __saturatef((thr - dwmin) * inv_ramp);
                float frac = wt*wt*(3.0f - 2.0f*wt);
                sum1 = fmaf(lk, frac, sum1);
            } while (m);
        }
    }

    // ---- block reduction -> 2 atomics ----
    int lane = tid & 31, wid = tid >> 5;
    #pragma unroll
    for (int o = 16; o; o >>= 1) {
        sum0 += __shfl_xor_sync(0xffffffffu, sum0, o);
        sum1 += __shfl_xor_sync(0xffffffffu, sum1, o);
    }
    if (lane == 0) s_red[wid] = make_float2(sum0, sum1);
    __syncthreads();
    if (wid == 0) {
        float a = (lane < SPB_/32) ? s_red[lane].x : 0.0f;
        float b = (lane < SPB_/32) ? s_red[lane].y : 0.0f;
        #pragma unroll
        for (int o = 4; o; o >>= 1) {
            a += __shfl_xor_sync(0xffffffffu, a, o);
            b += __shfl_xor_sync(0xffffffffu, b, o);
        }
        if (lane == 0) {
            atomicAdd(&out[p],      a);   // component 0, pose p
            atomicAdd(&out[P_ + p], b);   // component 1, pose p
        }
    }
}

// ---------------- launch ----------------
extern "C" void kernel_launch(void* const* d_in, const int* in_sizes, int n_in,
                              void* d_out, int out_size)
{
    const float* coords    = (const float*)d_in[0];
    const int*   blockType = (const int*)  d_in[1];
    const int*   minsep    = (const int*)  d_in[2];
    // d_in[3] = bt_n_atoms (unused: always A)
    const int*   bonds     = (const int*)  d_in[4];
    const int*   ranges    = (const int*)  d_in[5];
    const int*   n_donH    = (const int*)  d_in[6];
    const int*   n_acc     = (const int*)  d_in[7];
    const int*   donH      = (const int*)  d_in[8];
    const int*   don_hvy   = (const int*)  d_in[9];
    const int*   acc_inds  = (const int*)  d_in[10];
    const int*   hyb       = (const int*)  d_in[11];
    const int*   is_h      = (const int*)  d_in[12];
    const float* par4      = (const float*)d_in[13];
    const int*   pathd     = (const int*)  d_in[14];
    const float* gp        = (const float*)d_in[15];
    const float* wg        = (const float*)d_in[16];
    const float* sp2t      = (const float*)d_in[17];
    const float* sp3t      = (const float*)d_in[18];
    const float* ringt     = (const float*)d_in[19];
    float* out = (float*)d_out;

    prep_kernel<<<(NSITES_ + 127)/128, 128>>>(
        coords, blockType, bonds, ranges, n_donH, n_acc,
        donH, don_hvy, acc_inds, hyb, par4, pathd,
        wg, sp2t, sp3t, ringt, out);

    // pair kernel with programmatic dependent launch: prefix overlaps prep
    cudaLaunchConfig_t cfg = {};
    cfg.gridDim  = dim3(NBLK_, 1, 1);
    cfg.blockDim = dim3(SPB_, 1, 1);
    cfg.dynamicSmemBytes = 0;
    cfg.stream = 0;
    cudaLaunchAttribute attrs[1];
    attrs[0].id = cudaLaunchAttributeProgrammaticStreamSerialization;
    attrs[0].val.programmaticStreamSerializationAllowed = 1;
    cfg.attrs = attrs;
    cfg.numAttrs = 1;
    cudaLaunchKernelEx(&cfg, pair_kernel,
                       coords, blockType, minsep, is_h, par4, gp, out);
}